// round 2
// baseline (speedup 1.0000x reference)
#include <cuda_runtime.h>

// Scratch in __device__ globals (allocation is forbidden).
// g_partials[b] is overwritten by block b on every run -> no zeroing needed.
// g_count self-resets via atomicInc wraparound -> graph-replay safe.
#define MAX_BLOCKS 2048
__device__ float        g_partials[MAX_BLOCKS];
__device__ unsigned int g_count = 0;

__global__ __launch_bounds__(256)
void giou_fused_kernel(const float4* __restrict__ pred,
                       const float4* __restrict__ targ,
                       float* __restrict__ out,
                       int n, double inv_n) {
    float local = 0.0f;
    const int stride = gridDim.x * blockDim.x;
    for (int i = blockIdx.x * blockDim.x + threadIdx.x; i < n; i += stride) {
        const float4 p = __ldg(pred + i);   // x1,y1,x2,y2
        const float4 t = __ldg(targ + i);

        const float area_p = (p.z - p.x) * (p.w - p.y);
        const float area_t = (t.z - t.x) * (t.w - t.y);

        const float iw = fmaxf(fminf(p.z, t.z) - fmaxf(p.x, t.x), 0.0f);
        const float ih = fmaxf(fminf(p.w, t.w) - fmaxf(p.y, t.y), 0.0f);
        const float inter = iw * ih;
        const float uni   = area_p + area_t - inter;
        const float iou   = inter / uni;

        const float ew = fmaxf(fmaxf(p.z, t.z) - fminf(p.x, t.x), 0.0f);
        const float eh = fmaxf(fmaxf(p.w, t.w) - fminf(p.y, t.y), 0.0f);
        const float enc = ew * eh;

        const float giou = iou - (enc - uni) / enc;
        local += 1.0f - giou;
    }

    // intra-warp reduce
    #pragma unroll
    for (int off = 16; off > 0; off >>= 1)
        local += __shfl_down_sync(0xffffffffu, local, off);

    __shared__ float warp_sums[8];
    __shared__ bool  is_last;
    const int lane = threadIdx.x & 31;
    const int wid  = threadIdx.x >> 5;
    if (lane == 0) warp_sums[wid] = local;
    __syncthreads();

    if (wid == 0) {
        local = (lane < (blockDim.x >> 5)) ? warp_sums[lane] : 0.0f;
        #pragma unroll
        for (int off = 4; off > 0; off >>= 1)
            local += __shfl_down_sync(0xffu, local, off);
        if (lane == 0) {
            g_partials[blockIdx.x] = local;
            __threadfence();  // make partial visible before signaling
            unsigned int prev = atomicInc(&g_count, gridDim.x - 1);
            is_last = (prev == gridDim.x - 1);   // counter is now 0 again
        }
    }
    __syncthreads();

    if (is_last) {
        // Last block: sum all partials in fp64, write the mean.
        double acc = 0.0;
        for (int i = threadIdx.x; i < (int)gridDim.x; i += blockDim.x)
            acc += (double)__ldcg(&g_partials[i]);   // bypass L1: see peers' writes

        // warp reduce in fp64
        #pragma unroll
        for (int off = 16; off > 0; off >>= 1)
            acc += __shfl_down_sync(0xffffffffu, acc, off);

        __shared__ double dwarp[8];
        if (lane == 0) dwarp[wid] = acc;
        __syncthreads();
        if (wid == 0) {
            acc = (lane < (blockDim.x >> 5)) ? dwarp[lane] : 0.0;
            #pragma unroll
            for (int off = 4; off > 0; off >>= 1)
                acc += __shfl_down_sync(0xffu, acc, off);
            if (lane == 0)
                out[0] = (float)(acc * inv_n);
        }
    }
}

extern "C" void kernel_launch(void* const* d_in, const int* in_sizes, int n_in,
                              void* d_out, int out_size) {
    const float4* pred = (const float4*)d_in[0];
    const float4* targ = (const float4*)d_in[1];
    const int n = in_sizes[0] / 4;   // 4 floats per box

    const int threads = 256;
    int blocks = (n + threads - 1) / threads;
    if (blocks > MAX_BLOCKS) blocks = MAX_BLOCKS;

    giou_fused_kernel<<<blocks, threads>>>(pred, targ, (float*)d_out,
                                           n, 1.0 / (double)n);
}

// round 3
// speedup vs baseline: 1.1941x; 1.1941x over previous
#include <cuda_runtime.h>

// Scratch in __device__ globals (allocation is forbidden).
// g_partials[b] overwritten every run; g_count self-resets via atomicInc wrap.
#define MAX_BLOCKS 2048
__device__ float        g_partials[MAX_BLOCKS];
__device__ unsigned int g_count = 0;

__device__ __forceinline__ float giou_term(const float4 p, const float4 t) {
    const float area_p = (p.z - p.x) * (p.w - p.y);
    const float area_t = (t.z - t.x) * (t.w - t.y);

    const float iw = fmaxf(fminf(p.z, t.z) - fmaxf(p.x, t.x), 0.0f);
    const float ih = fmaxf(fminf(p.w, t.w) - fmaxf(p.y, t.y), 0.0f);
    const float inter = iw * ih;
    const float uni   = area_p + area_t - inter;

    const float ew = fmaxf(fmaxf(p.z, t.z) - fminf(p.x, t.x), 0.0f);
    const float eh = fmaxf(fmaxf(p.w, t.w) - fminf(p.y, t.y), 0.0f);
    const float enc = ew * eh;

    // 1 - giou = 1 - inter/uni + (enc - uni)/enc
    const float iou  = __fdividef(inter, uni);
    const float pen  = __fdividef(enc - uni, enc);
    return 1.0f - iou + pen;
}

__global__ __launch_bounds__(256)
void giou_fused_kernel(const float4* __restrict__ pred,
                       const float4* __restrict__ targ,
                       float* __restrict__ out,
                       int n, double inv_n) {
    float local = 0.0f;
    const int stride = gridDim.x * blockDim.x;
    int i = blockIdx.x * blockDim.x + threadIdx.x;

    // Main loop: 8 independent LDG.128 batched up front (MLP_p1 = 8).
    for (; i + 3 * stride < n; i += 4 * stride) {
        const float4 p0 = __ldg(pred + i);
        const float4 p1 = __ldg(pred + i + stride);
        const float4 p2 = __ldg(pred + i + 2 * stride);
        const float4 p3 = __ldg(pred + i + 3 * stride);
        const float4 t0 = __ldg(targ + i);
        const float4 t1 = __ldg(targ + i + stride);
        const float4 t2 = __ldg(targ + i + 2 * stride);
        const float4 t3 = __ldg(targ + i + 3 * stride);

        local += giou_term(p0, t0);
        local += giou_term(p1, t1);
        local += giou_term(p2, t2);
        local += giou_term(p3, t3);
    }
    // Tail
    for (; i < n; i += stride)
        local += giou_term(__ldg(pred + i), __ldg(targ + i));

    // intra-warp reduce
    #pragma unroll
    for (int off = 16; off > 0; off >>= 1)
        local += __shfl_down_sync(0xffffffffu, local, off);

    __shared__ float warp_sums[8];
    __shared__ bool  is_last;
    const int lane = threadIdx.x & 31;
    const int wid  = threadIdx.x >> 5;
    if (lane == 0) warp_sums[wid] = local;
    __syncthreads();

    if (wid == 0) {
        local = (lane < (blockDim.x >> 5)) ? warp_sums[lane] : 0.0f;
        #pragma unroll
        for (int off = 4; off > 0; off >>= 1)
            local += __shfl_down_sync(0xffu, local, off);
        if (lane == 0) {
            g_partials[blockIdx.x] = local;
            __threadfence();
            unsigned int prev = atomicInc(&g_count, gridDim.x - 1);
            is_last = (prev == gridDim.x - 1);
        }
    }
    __syncthreads();

    if (is_last) {
        double acc = 0.0;
        for (int k = threadIdx.x; k < (int)gridDim.x; k += blockDim.x)
            acc += (double)__ldcg(&g_partials[k]);

        #pragma unroll
        for (int off = 16; off > 0; off >>= 1)
            acc += __shfl_down_sync(0xffffffffu, acc, off);

        __shared__ double dwarp[8];
        if (lane == 0) dwarp[wid] = acc;
        __syncthreads();
        if (wid == 0) {
            acc = (lane < (blockDim.x >> 5)) ? dwarp[lane] : 0.0;
            #pragma unroll
            for (int off = 4; off > 0; off >>= 1)
                acc += __shfl_down_sync(0xffu, acc, off);
            if (lane == 0)
                out[0] = (float)(acc * inv_n);
        }
    }
}

extern "C" void kernel_launch(void* const* d_in, const int* in_sizes, int n_in,
                              void* d_out, int out_size) {
    const float4* pred = (const float4*)d_in[0];
    const float4* targ = (const float4*)d_in[1];
    const int n = in_sizes[0] / 4;   // 4 floats per box

    const int threads = 256;
    // Exactly one wave: 148 SMs x 8 resident 256-thread CTAs.
    int blocks = 148 * 8;            // 1184
    int max_needed = (n + threads - 1) / threads;
    if (blocks > max_needed) blocks = max_needed;
    if (blocks > MAX_BLOCKS) blocks = MAX_BLOCKS;

    giou_fused_kernel<<<blocks, threads>>>(pred, targ, (float*)d_out,
                                           n, 1.0 / (double)n);
}